// round 13
// baseline (speedup 1.0000x reference)
#include <cuda_runtime.h>
#include <cuda_fp16.h>
#include <cstdint>
#include <cstddef>

#define H_DIM 4096
#define I_DIM 14336
#define M_DIM 1024

__device__ __align__(1024) __half g_gate_eff[(size_t)I_DIM * H_DIM];
__device__ __align__(1024) __half g_up_eff  [(size_t)I_DIM * H_DIM];
__device__ __align__(1024) __half g_down_eff[(size_t)H_DIM * I_DIM];
__device__ __align__(1024) __half g_mid     [(size_t)M_DIM * I_DIM];
__device__ __align__(1024) __half g_xr      [(size_t)M_DIM * H_DIM];

__device__ __forceinline__ uint32_t smem_u32(const void* p) {
    uint32_t a;
    asm("{ .reg .u64 t; cvta.to.shared.u64 t, %1; cvt.u32.u64 %0, t; }" : "=r"(a) : "l"(p));
    return a;
}
#define CP_ASYNC16(dst, src) \
    asm volatile("cp.async.cg.shared.global [%0], [%1], 16;" :: "r"(dst), "l"(src) : "memory")
#define CP_COMMIT() asm volatile("cp.async.commit_group;" ::: "memory")
#define CP_WAIT1()  asm volatile("cp.async.wait_group 1;" ::: "memory")
#define CP_WAIT0()  asm volatile("cp.async.wait_group 0;" ::: "memory")

#define LDSM4(r0, r1, r2, r3, a) \
    asm volatile("ldmatrix.sync.aligned.m8n8.x4.shared.b16 {%0,%1,%2,%3}, [%4];" \
        : "=r"(r0), "=r"(r1), "=r"(r2), "=r"(r3) : "r"(a))

__device__ __forceinline__ void mma16(float* c, uint32_t a0, uint32_t a1, uint32_t a2,
                                      uint32_t a3, uint32_t b0, uint32_t b1) {
    asm volatile(
        "mma.sync.aligned.m16n8k16.row.col.f32.f16.f16.f32 "
        "{%0,%1,%2,%3}, {%4,%5,%6,%7}, {%8,%9}, {%0,%1,%2,%3};"
        : "+f"(c[0]), "+f"(c[1]), "+f"(c[2]), "+f"(c[3])
        : "r"(a0), "r"(a1), "r"(a2), "r"(a3), "r"(b0), "r"(b1));
}

__device__ __forceinline__ uint32_t pack_h2(float lo, float hi) {
    __half2 h = __floats2half2_rn(lo, hi);
    return *reinterpret_cast<uint32_t*>(&h);
}

// ---------------- elementwise: W_eff = W * (su@sv), fp32 -> fp16 ----------------
template <int IND>
__global__ void __launch_bounds__(256) eff_row(const float* __restrict__ w,
                                               const float* __restrict__ su,
                                               const float* __restrict__ sv,
                                               __half* __restrict__ dst) {
    int o = blockIdx.x;
    float s0 = su[(size_t)o * 4 + 0], s1 = su[(size_t)o * 4 + 1];
    float s2 = su[(size_t)o * 4 + 2], s3 = su[(size_t)o * 4 + 3];
    const float4* wr = (const float4*)(w + (size_t)o * IND);
    uint2* dr = (uint2*)(dst + (size_t)o * IND);
    const float4* v0 = (const float4*)(sv);
    const float4* v1 = (const float4*)(sv + IND);
    const float4* v2 = (const float4*)(sv + 2 * IND);
    const float4* v3 = (const float4*)(sv + 3 * IND);
#pragma unroll 2
    for (int i = threadIdx.x; i < IND / 4; i += 256) {
        float4 wv = wr[i];
        float4 a = v0[i], b = v1[i], c = v2[i], d = v3[i];
        uint2 ov;
        ov.x = pack_h2(wv.x * (s0 * a.x + s1 * b.x + s2 * c.x + s3 * d.x),
                       wv.y * (s0 * a.y + s1 * b.y + s2 * c.y + s3 * d.y));
        ov.y = pack_h2(wv.z * (s0 * a.z + s1 * b.z + s2 * c.z + s3 * d.z),
                       wv.w * (s0 * a.w + s1 * b.w + s2 * c.w + s3 * d.w));
        dr[i] = ov;
    }
}

__global__ void x_to_half(const float* __restrict__ src, __half* __restrict__ dst, size_t n4) {
    for (size_t i = (size_t)blockIdx.x * blockDim.x + threadIdx.x; i < n4;
         i += (size_t)gridDim.x * blockDim.x) {
        float4 v = reinterpret_cast<const float4*>(src)[i];
        uint2 o;
        o.x = pack_h2(v.x, v.y);
        o.y = pack_h2(v.z, v.w);
        reinterpret_cast<uint2*>(dst)[i] = o;
    }
}

// ---------------- GEMM tiling: fp16, BM=128, BK=64, 128 threads, 2x2 warps ------
#define SROWH 72
#define ROWB  144
#define STAGE_B (256 * ROWB)            // 36864 B
#define GEMM_SMEM (2 * STAGE_B)         // 73728 B -> 2 CTAs/SM

// 128 rows with 128 threads: 8 iters
__device__ __forceinline__ void load_rows128(uint32_t sdst, const __half* __restrict__ g,
                                             int stride, int tid) {
#pragma unroll
    for (int i = 0; i < 8; i++) {
        int c = tid + i * 128;
        int row = c >> 3, seg = c & 7;
        CP_ASYNC16(sdst + (uint32_t)(row * ROWB + seg * 16),
                   g + (size_t)row * stride + seg * 8);
    }
}
// 64 rows with 128 threads: 4 iters
__device__ __forceinline__ void load_rows64(uint32_t sdst, const __half* __restrict__ g,
                                            int stride, int tid) {
#pragma unroll
    for (int i = 0; i < 4; i++) {
        int c = tid + i * 128;
        int row = c >> 3, seg = c & 7;
        CP_ASYNC16(sdst + (uint32_t)(row * ROWB + seg * 16),
                   g + (size_t)row * stride + seg * 8);
    }
}

// ---------------- fused gate+up GEMM + SwiGLU -> g_mid (fp16) ----------------
// BM=128, BN=64, BK=64. 2x2 warps; warp tile m64 x n32 per gemm.
__global__ void __launch_bounds__(128, 2) gemm_gateup() {
    extern __shared__ uint32_t smem[];
    uint32_t sb = smem_u32(smem);
    int tid = threadIdx.x, lane = tid & 31, wid = tid >> 5;
    int mt = blockIdx.x, nt = blockIdx.y;
    int warp_m = wid & 1, warp_n = wid >> 1;
    int g = lane >> 2, t = lane & 3;
    const __half* Ag = g_xr + (size_t)mt * 128 * H_DIM;
    const __half* Gg = g_gate_eff + (size_t)nt * 64 * H_DIM;
    const __half* Ug = g_up_eff + (size_t)nt * 64 * H_DIM;
    const int KT = H_DIM / 64;

    int m8 = lane >> 3, r8 = lane & 7;
    uint32_t a_off[4];
#pragma unroll
    for (int i = 0; i < 4; i++)
        a_off[i] = (uint32_t)(((warp_m * 64 + i * 16 + (m8 & 1) * 8 + r8) * SROWH +
                               (m8 >> 1) * 8) * 2);
    uint32_t b_off[2];
#pragma unroll
    for (int h = 0; h < 2; h++)
        b_off[h] = (uint32_t)(((warp_n * 32 + h * 16 + (m8 >> 1) * 8 + r8) * SROWH +
                               (m8 & 1) * 8) * 2);

    float accg[4][4][4] = {}, accu[4][4][4] = {};

    load_rows128(sb, Ag, H_DIM, tid);
    load_rows64(sb + 128 * ROWB, Gg, H_DIM, tid);
    load_rows64(sb + 192 * ROWB, Ug, H_DIM, tid);
    CP_COMMIT();

    for (int kt = 0; kt < KT; kt++) {
        int buf = kt & 1;
        if (kt + 1 < KT) {
            uint32_t nb = sb + (buf ^ 1) * STAGE_B;
            int k0 = (kt + 1) * 64;
            load_rows128(nb, Ag + k0, H_DIM, tid);
            load_rows64(nb + 128 * ROWB, Gg + k0, H_DIM, tid);
            load_rows64(nb + 192 * ROWB, Ug + k0, H_DIM, tid);
            CP_COMMIT(); CP_WAIT1();
        } else CP_WAIT0();
        __syncthreads();

        uint32_t stg = sb + buf * STAGE_B;
#pragma unroll
        for (int kk = 0; kk < 4; kk++) {
            uint32_t kb = stg + kk * 32;
            uint32_t a0[4], a1[4], a2[4], a3[4];
            uint32_t bg0[4], bg1[4], bu0[4], bu1[4];
#pragma unroll
            for (int i = 0; i < 4; i++)
                LDSM4(a0[i], a1[i], a2[i], a3[i], kb + a_off[i]);
#pragma unroll
            for (int h = 0; h < 2; h++) {
                LDSM4(bg0[2 * h], bg1[2 * h], bg0[2 * h + 1], bg1[2 * h + 1],
                      kb + 128 * ROWB + b_off[h]);
                LDSM4(bu0[2 * h], bu1[2 * h], bu0[2 * h + 1], bu1[2 * h + 1],
                      kb + 192 * ROWB + b_off[h]);
            }
#pragma unroll
            for (int i = 0; i < 4; i++)
#pragma unroll
                for (int j = 0; j < 4; j++) {
                    mma16(accg[i][j], a0[i], a1[i], a2[i], a3[i], bg0[j], bg1[j]);
                    mma16(accu[i][j], a0[i], a1[i], a2[i], a3[i], bu0[j], bu1[j]);
                }
        }
        __syncthreads();
    }

    // SwiGLU epilogue -> g_mid fp16
#pragma unroll
    for (int i = 0; i < 4; i++) {
        int r0 = mt * 128 + warp_m * 64 + i * 16 + g;
#pragma unroll
        for (int j = 0; j < 4; j++) {
            int cc = nt * 64 + warp_n * 32 + j * 8 + t * 2;
            float ga = accg[i][j][0], gb = accg[i][j][1];
            float gc = accg[i][j][2], gd = accg[i][j][3];
            float v0 = (ga / (1.f + __expf(-ga))) * accu[i][j][0];
            float v1 = (gb / (1.f + __expf(-gb))) * accu[i][j][1];
            float v2 = (gc / (1.f + __expf(-gc))) * accu[i][j][2];
            float v3 = (gd / (1.f + __expf(-gd))) * accu[i][j][3];
            *(uint32_t*)(g_mid + (size_t)r0 * I_DIM + cc) = pack_h2(v0, v1);
            *(uint32_t*)(g_mid + (size_t)(r0 + 8) * I_DIM + cc) = pack_h2(v2, v3);
        }
    }
}

// ---------------- down GEMM (fp16 in, fp32 out) ----------------
// BM=128, BN=128, BK=64. 2x2 warps; warp tile m64 x n64.
__global__ void __launch_bounds__(128, 2) gemm_down(float* __restrict__ out) {
    extern __shared__ uint32_t smem[];
    uint32_t sb = smem_u32(smem);
    int tid = threadIdx.x, lane = tid & 31, wid = tid >> 5;
    int mt = blockIdx.x, nt = blockIdx.y;
    int warp_m = wid & 1, warp_n = wid >> 1;
    int g = lane >> 2, t = lane & 3;
    const __half* Ag = g_mid + (size_t)mt * 128 * I_DIM;
    const __half* Bg = g_down_eff + (size_t)nt * 128 * I_DIM;
    const int KT = I_DIM / 64;

    int m8 = lane >> 3, r8 = lane & 7;
    uint32_t a_off[4];
#pragma unroll
    for (int i = 0; i < 4; i++)
        a_off[i] = (uint32_t)(((warp_m * 64 + i * 16 + (m8 & 1) * 8 + r8) * SROWH +
                               (m8 >> 1) * 8) * 2);
    uint32_t b_off[4];
#pragma unroll
    for (int h = 0; h < 4; h++)
        b_off[h] = (uint32_t)(((warp_n * 64 + h * 16 + (m8 >> 1) * 8 + r8) * SROWH +
                               (m8 & 1) * 8) * 2);

    float acc[4][8][4] = {};

    load_rows128(sb, Ag, I_DIM, tid);
    load_rows128(sb + 128 * ROWB, Bg, I_DIM, tid);
    CP_COMMIT();

    for (int kt = 0; kt < KT; kt++) {
        int buf = kt & 1;
        if (kt + 1 < KT) {
            uint32_t nb = sb + (buf ^ 1) * STAGE_B;
            int k0 = (kt + 1) * 64;
            load_rows128(nb, Ag + k0, I_DIM, tid);
            load_rows128(nb + 128 * ROWB, Bg + k0, I_DIM, tid);
            CP_COMMIT(); CP_WAIT1();
        } else CP_WAIT0();
        __syncthreads();

        uint32_t stg = sb + buf * STAGE_B;
#pragma unroll
        for (int kk = 0; kk < 4; kk++) {
            uint32_t kb = stg + kk * 32;
            uint32_t a0[4], a1[4], a2[4], a3[4], b0[8], b1[8];
#pragma unroll
            for (int i = 0; i < 4; i++)
                LDSM4(a0[i], a1[i], a2[i], a3[i], kb + a_off[i]);
#pragma unroll
            for (int h = 0; h < 4; h++)
                LDSM4(b0[2 * h], b1[2 * h], b0[2 * h + 1], b1[2 * h + 1],
                      kb + 128 * ROWB + b_off[h]);
#pragma unroll
            for (int i = 0; i < 4; i++)
#pragma unroll
                for (int j = 0; j < 8; j++)
                    mma16(acc[i][j], a0[i], a1[i], a2[i], a3[i], b0[j], b1[j]);
        }
        __syncthreads();
    }

#pragma unroll
    for (int i = 0; i < 4; i++) {
        int r0 = mt * 128 + warp_m * 64 + i * 16 + g;
#pragma unroll
        for (int j = 0; j < 8; j++) {
            int cc = nt * 128 + warp_n * 64 + j * 8 + t * 2;
            *(float2*)(out + (size_t)r0 * H_DIM + cc) = make_float2(acc[i][j][0], acc[i][j][1]);
            *(float2*)(out + (size_t)(r0 + 8) * H_DIM + cc) = make_float2(acc[i][j][2], acc[i][j][3]);
        }
    }
}

// ---------------- launch ----------------
extern "C" void kernel_launch(void* const* d_in, const int* in_sizes, int n_in,
                              void* d_out, int out_size) {
    (void)in_sizes; (void)n_in; (void)out_size;
    const float* x       = (const float*)d_in[0];
    const float* gate_w  = (const float*)d_in[1];
    const float* gate_su = (const float*)d_in[2];
    const float* gate_sv = (const float*)d_in[3];
    const float* up_w    = (const float*)d_in[4];
    const float* up_su   = (const float*)d_in[5];
    const float* up_sv   = (const float*)d_in[6];
    const float* down_w  = (const float*)d_in[7];
    const float* down_su = (const float*)d_in[8];
    const float* down_sv = (const float*)d_in[9];
    float* out = (float*)d_out;

    void *pg, *pu, *pd, *pxr;
    cudaGetSymbolAddress(&pg, g_gate_eff);
    cudaGetSymbolAddress(&pu, g_up_eff);
    cudaGetSymbolAddress(&pd, g_down_eff);
    cudaGetSymbolAddress(&pxr, g_xr);

    cudaFuncSetAttribute(gemm_gateup, cudaFuncAttributeMaxDynamicSharedMemorySize, GEMM_SMEM);
    cudaFuncSetAttribute(gemm_down,   cudaFuncAttributeMaxDynamicSharedMemorySize, GEMM_SMEM);

    eff_row<H_DIM><<<I_DIM, 256>>>(gate_w, gate_su, gate_sv, (__half*)pg);
    eff_row<H_DIM><<<I_DIM, 256>>>(up_w,   up_su,   up_sv,   (__half*)pu);
    eff_row<I_DIM><<<H_DIM, 256>>>(down_w, down_su, down_sv, (__half*)pd);
    x_to_half<<<592, 256>>>(x, (__half*)pxr, (size_t)M_DIM * H_DIM / 4);

    gemm_gateup<<<dim3(M_DIM / 128, I_DIM / 64), 128, GEMM_SMEM>>>();
    gemm_down<<<dim3(M_DIM / 128, H_DIM / 128), 128, GEMM_SMEM>>>(out);
}

// round 14
// speedup vs baseline: 1.0447x; 1.0447x over previous
#include <cuda_runtime.h>
#include <cuda_fp16.h>
#include <cstdint>
#include <cstddef>

#define H_DIM 4096
#define I_DIM 14336
#define M_DIM 1024

__device__ __align__(1024) __half g_gate_eff[(size_t)I_DIM * H_DIM];
__device__ __align__(1024) __half g_up_eff  [(size_t)I_DIM * H_DIM];
__device__ __align__(1024) __half g_down_eff[(size_t)H_DIM * I_DIM];
__device__ __align__(1024) __half g_mid     [(size_t)M_DIM * I_DIM];
__device__ __align__(1024) __half g_xr      [(size_t)M_DIM * H_DIM];

__device__ __forceinline__ uint32_t smem_u32(const void* p) {
    uint32_t a;
    asm("{ .reg .u64 t; cvta.to.shared.u64 t, %1; cvt.u32.u64 %0, t; }" : "=r"(a) : "l"(p));
    return a;
}
#define CP_ASYNC16(dst, src) \
    asm volatile("cp.async.cg.shared.global [%0], [%1], 16;" :: "r"(dst), "l"(src) : "memory")
#define CP_COMMIT() asm volatile("cp.async.commit_group;" ::: "memory")
#define CP_WAIT1()  asm volatile("cp.async.wait_group 1;" ::: "memory")
#define CP_WAIT0()  asm volatile("cp.async.wait_group 0;" ::: "memory")

#define LDSM4(r0, r1, r2, r3, a) \
    asm volatile("ldmatrix.sync.aligned.m8n8.x4.shared.b16 {%0,%1,%2,%3}, [%4];" \
        : "=r"(r0), "=r"(r1), "=r"(r2), "=r"(r3) : "r"(a))

__device__ __forceinline__ void mma16(float* c, uint32_t a0, uint32_t a1, uint32_t a2,
                                      uint32_t a3, uint32_t b0, uint32_t b1) {
    asm volatile(
        "mma.sync.aligned.m16n8k16.row.col.f32.f16.f16.f32 "
        "{%0,%1,%2,%3}, {%4,%5,%6,%7}, {%8,%9}, {%0,%1,%2,%3};"
        : "+f"(c[0]), "+f"(c[1]), "+f"(c[2]), "+f"(c[3])
        : "r"(a0), "r"(a1), "r"(a2), "r"(a3), "r"(b0), "r"(b1));
}

__device__ __forceinline__ uint32_t pack_h2(float lo, float hi) {
    __half2 h = __floats2half2_rn(lo, hi);
    return *reinterpret_cast<uint32_t*>(&h);
}

// ---------------- elementwise: W_eff = W * (su@sv), fp32 -> fp16 ----------------
template <int IND>
__global__ void __launch_bounds__(256) eff_row(const float* __restrict__ w,
                                               const float* __restrict__ su,
                                               const float* __restrict__ sv,
                                               __half* __restrict__ dst) {
    int o = blockIdx.x;
    float s0 = su[(size_t)o * 4 + 0], s1 = su[(size_t)o * 4 + 1];
    float s2 = su[(size_t)o * 4 + 2], s3 = su[(size_t)o * 4 + 3];
    const float4* wr = (const float4*)(w + (size_t)o * IND);
    uint2* dr = (uint2*)(dst + (size_t)o * IND);
    const float4* v0 = (const float4*)(sv);
    const float4* v1 = (const float4*)(sv + IND);
    const float4* v2 = (const float4*)(sv + 2 * IND);
    const float4* v3 = (const float4*)(sv + 3 * IND);
#pragma unroll 2
    for (int i = threadIdx.x; i < IND / 4; i += 256) {
        float4 wv = wr[i];
        float4 a = v0[i], b = v1[i], c = v2[i], d = v3[i];
        uint2 ov;
        ov.x = pack_h2(wv.x * (s0 * a.x + s1 * b.x + s2 * c.x + s3 * d.x),
                       wv.y * (s0 * a.y + s1 * b.y + s2 * c.y + s3 * d.y));
        ov.y = pack_h2(wv.z * (s0 * a.z + s1 * b.z + s2 * c.z + s3 * d.z),
                       wv.w * (s0 * a.w + s1 * b.w + s2 * c.w + s3 * d.w));
        dr[i] = ov;
    }
}

__global__ void x_to_half(const float* __restrict__ src, __half* __restrict__ dst, size_t n4) {
    for (size_t i = (size_t)blockIdx.x * blockDim.x + threadIdx.x; i < n4;
         i += (size_t)gridDim.x * blockDim.x) {
        float4 v = reinterpret_cast<const float4*>(src)[i];
        uint2 o;
        o.x = pack_h2(v.x, v.y);
        o.y = pack_h2(v.z, v.w);
        reinterpret_cast<uint2*>(dst)[i] = o;
    }
}

// ---------------- GEMM tiling: fp16, BM=128, BK=64, 256 threads (R9 best) -------
#define SROWH 72
#define ROWB  144
#define STAGE_B (256 * ROWB)            // 36864 B
#define GEMM_SMEM (2 * STAGE_B)         // 73728 B -> 2 CTAs/SM

__device__ __forceinline__ void load_rows128(uint32_t sdst, const __half* __restrict__ g,
                                             int stride, int tid) {
#pragma unroll
    for (int i = 0; i < 4; i++) {
        int c = tid + i * 256;
        int row = c >> 3, seg = c & 7;
        CP_ASYNC16(sdst + (uint32_t)(row * ROWB + seg * 16),
                   g + (size_t)row * stride + seg * 8);
    }
}
__device__ __forceinline__ void load_rows64(uint32_t sdst, const __half* __restrict__ g,
                                            int stride, int tid) {
#pragma unroll
    for (int i = 0; i < 2; i++) {
        int c = tid + i * 256;
        int row = c >> 3, seg = c & 7;
        CP_ASYNC16(sdst + (uint32_t)(row * ROWB + seg * 16),
                   g + (size_t)row * stride + seg * 8);
    }
}

// ---------------- fused gate+up GEMM + SwiGLU -> g_mid (fp16) ----------------
// BM=128, BN=64, BK=64. 2x4 warps; warp tile 64x16 per gemm.
__global__ void __launch_bounds__(256, 2) gemm_gateup() {
    extern __shared__ uint32_t smem[];
    uint32_t sb = smem_u32(smem);
    int tid = threadIdx.x, lane = tid & 31, wid = tid >> 5;
    int mt = blockIdx.x, nt = blockIdx.y;
    int warp_m = wid & 1, warp_n = wid >> 1;
    int g = lane >> 2, t = lane & 3;
    const __half* Ag = g_xr + (size_t)mt * 128 * H_DIM;
    const __half* Gg = g_gate_eff + (size_t)nt * 64 * H_DIM;
    const __half* Ug = g_up_eff + (size_t)nt * 64 * H_DIM;
    const int KT = H_DIM / 64;

    int m8 = lane >> 3, r8 = lane & 7;
    uint32_t a_off[4];
#pragma unroll
    for (int i = 0; i < 4; i++)
        a_off[i] = (uint32_t)(((warp_m * 64 + i * 16 + (m8 & 1) * 8 + r8) * SROWH +
                               (m8 >> 1) * 8) * 2);
    uint32_t b_off = (uint32_t)(((warp_n * 16 + (m8 >> 1) * 8 + r8) * SROWH +
                                 (m8 & 1) * 8) * 2);

    float accg[4][2][4] = {}, accu[4][2][4] = {};

    load_rows128(sb, Ag, H_DIM, tid);
    load_rows64(sb + 128 * ROWB, Gg, H_DIM, tid);
    load_rows64(sb + 192 * ROWB, Ug, H_DIM, tid);
    CP_COMMIT();

    for (int kt = 0; kt < KT; kt++) {
        int buf = kt & 1;
        if (kt + 1 < KT) {
            uint32_t nb = sb + (buf ^ 1) * STAGE_B;
            int k0 = (kt + 1) * 64;
            load_rows128(nb, Ag + k0, H_DIM, tid);
            load_rows64(nb + 128 * ROWB, Gg + k0, H_DIM, tid);
            load_rows64(nb + 192 * ROWB, Ug + k0, H_DIM, tid);
            CP_COMMIT(); CP_WAIT1();
        } else CP_WAIT0();
        __syncthreads();

        uint32_t stg = sb + buf * STAGE_B;
#pragma unroll
        for (int kk = 0; kk < 4; kk++) {
            uint32_t kb = stg + kk * 32;
            uint32_t a0[4], a1[4], a2[4], a3[4];
            uint32_t bg0[2], bg1[2], bu0[2], bu1[2];
#pragma unroll
            for (int i = 0; i < 4; i++)
                LDSM4(a0[i], a1[i], a2[i], a3[i], kb + a_off[i]);
            LDSM4(bg0[0], bg1[0], bg0[1], bg1[1], kb + 128 * ROWB + b_off);
            LDSM4(bu0[0], bu1[0], bu0[1], bu1[1], kb + 192 * ROWB + b_off);
#pragma unroll
            for (int i = 0; i < 4; i++)
#pragma unroll
                for (int j = 0; j < 2; j++) {
                    mma16(accg[i][j], a0[i], a1[i], a2[i], a3[i], bg0[j], bg1[j]);
                    mma16(accu[i][j], a0[i], a1[i], a2[i], a3[i], bu0[j], bu1[j]);
                }
        }
        __syncthreads();
    }

    // SwiGLU epilogue -> g_mid fp16
#pragma unroll
    for (int i = 0; i < 4; i++) {
        int r0 = mt * 128 + warp_m * 64 + i * 16 + g;
#pragma unroll
        for (int j = 0; j < 2; j++) {
            int cc = nt * 64 + warp_n * 16 + j * 8 + t * 2;
            float ga = accg[i][j][0], gb = accg[i][j][1];
            float gc = accg[i][j][2], gd = accg[i][j][3];
            float v0 = (ga / (1.f + __expf(-ga))) * accu[i][j][0];
            float v1 = (gb / (1.f + __expf(-gb))) * accu[i][j][1];
            float v2 = (gc / (1.f + __expf(-gc))) * accu[i][j][2];
            float v3 = (gd / (1.f + __expf(-gd))) * accu[i][j][3];
            *(uint32_t*)(g_mid + (size_t)r0 * I_DIM + cc) = pack_h2(v0, v1);
            *(uint32_t*)(g_mid + (size_t)(r0 + 8) * I_DIM + cc) = pack_h2(v2, v3);
        }
    }
}

// ---------------- down GEMM (fp16 in, fp32 out) ----------------
// BM=128, BN=128, BK=64. 2x4 warps; warp tile 64x32.
__global__ void __launch_bounds__(256, 2) gemm_down(float* __restrict__ out) {
    extern __shared__ uint32_t smem[];
    uint32_t sb = smem_u32(smem);
    int tid = threadIdx.x, lane = tid & 31, wid = tid >> 5;
    int mt = blockIdx.x, nt = blockIdx.y;
    int warp_m = wid & 1, warp_n = wid >> 1;
    int g = lane >> 2, t = lane & 3;
    const __half* Ag = g_mid + (size_t)mt * 128 * I_DIM;
    const __half* Bg = g_down_eff + (size_t)nt * 128 * I_DIM;
    const int KT = I_DIM / 64;

    int m8 = lane >> 3, r8 = lane & 7;
    uint32_t a_off[4];
#pragma unroll
    for (int i = 0; i < 4; i++)
        a_off[i] = (uint32_t)(((warp_m * 64 + i * 16 + (m8 & 1) * 8 + r8) * SROWH +
                               (m8 >> 1) * 8) * 2);
    uint32_t b_off[2];
#pragma unroll
    for (int h = 0; h < 2; h++)
        b_off[h] = (uint32_t)(((warp_n * 32 + h * 16 + (m8 >> 1) * 8 + r8) * SROWH +
                               (m8 & 1) * 8) * 2);

    float acc[4][4][4] = {};

    load_rows128(sb, Ag, I_DIM, tid);
    load_rows128(sb + 128 * ROWB, Bg, I_DIM, tid);
    CP_COMMIT();

    for (int kt = 0; kt < KT; kt++) {
        int buf = kt & 1;
        if (kt + 1 < KT) {
            uint32_t nb = sb + (buf ^ 1) * STAGE_B;
            int k0 = (kt + 1) * 64;
            load_rows128(nb, Ag + k0, I_DIM, tid);
            load_rows128(nb + 128 * ROWB, Bg + k0, I_DIM, tid);
            CP_COMMIT(); CP_WAIT1();
        } else CP_WAIT0();
        __syncthreads();

        uint32_t stg = sb + buf * STAGE_B;
#pragma unroll
        for (int kk = 0; kk < 4; kk++) {
            uint32_t kb = stg + kk * 32;
            uint32_t a0[4], a1[4], a2[4], a3[4], b0[4], b1[4];
#pragma unroll
            for (int i = 0; i < 4; i++)
                LDSM4(a0[i], a1[i], a2[i], a3[i], kb + a_off[i]);
#pragma unroll
            for (int h = 0; h < 2; h++)
                LDSM4(b0[2 * h], b1[2 * h], b0[2 * h + 1], b1[2 * h + 1],
                      kb + 128 * ROWB + b_off[h]);
#pragma unroll
            for (int i = 0; i < 4; i++)
#pragma unroll
                for (int j = 0; j < 4; j++)
                    mma16(acc[i][j], a0[i], a1[i], a2[i], a3[i], b0[j], b1[j]);
        }
        __syncthreads();
    }

#pragma unroll
    for (int i = 0; i < 4; i++) {
        int r0 = mt * 128 + warp_m * 64 + i * 16 + g;
#pragma unroll
        for (int j = 0; j < 4; j++) {
            int cc = nt * 128 + warp_n * 32 + j * 8 + t * 2;
            *(float2*)(out + (size_t)r0 * H_DIM + cc) = make_float2(acc[i][j][0], acc[i][j][1]);
            *(float2*)(out + (size_t)(r0 + 8) * H_DIM + cc) = make_float2(acc[i][j][2], acc[i][j][3]);
        }
    }
}

// ---------------- launch: concurrent elementwise + hidden eff_down ----------------
extern "C" void kernel_launch(void* const* d_in, const int* in_sizes, int n_in,
                              void* d_out, int out_size) {
    (void)in_sizes; (void)n_in; (void)out_size;
    const float* x       = (const float*)d_in[0];
    const float* gate_w  = (const float*)d_in[1];
    const float* gate_su = (const float*)d_in[2];
    const float* gate_sv = (const float*)d_in[3];
    const float* up_w    = (const float*)d_in[4];
    const float* up_su   = (const float*)d_in[5];
    const float* up_sv   = (const float*)d_in[6];
    const float* down_w  = (const float*)d_in[7];
    const float* down_su = (const float*)d_in[8];
    const float* down_sv = (const float*)d_in[9];
    float* out = (float*)d_out;

    void *pg, *pu, *pd, *pxr;
    cudaGetSymbolAddress(&pg, g_gate_eff);
    cudaGetSymbolAddress(&pu, g_up_eff);
    cudaGetSymbolAddress(&pd, g_down_eff);
    cudaGetSymbolAddress(&pxr, g_xr);

    cudaFuncSetAttribute(gemm_gateup, cudaFuncAttributeMaxDynamicSharedMemorySize, GEMM_SMEM);
    cudaFuncSetAttribute(gemm_down,   cudaFuncAttributeMaxDynamicSharedMemorySize, GEMM_SMEM);

    // Side streams + events, created once on the first (non-capture) call.
    static cudaStream_t s1 = nullptr, s2 = nullptr, s3 = nullptr;
    static cudaEvent_t e_fork = nullptr, e_j1 = nullptr, e_j2 = nullptr, e_j3 = nullptr;
    if (!s1) {
        cudaStreamCreateWithFlags(&s1, cudaStreamNonBlocking);
        cudaStreamCreateWithFlags(&s2, cudaStreamNonBlocking);
        cudaStreamCreateWithFlags(&s3, cudaStreamNonBlocking);
        cudaEventCreateWithFlags(&e_fork, cudaEventDisableTiming);
        cudaEventCreateWithFlags(&e_j1, cudaEventDisableTiming);
        cudaEventCreateWithFlags(&e_j2, cudaEventDisableTiming);
        cudaEventCreateWithFlags(&e_j3, cudaEventDisableTiming);
    }

    // Fork: all elementwise kernels run concurrently.
    cudaEventRecord(e_fork, 0);
    cudaStreamWaitEvent(s1, e_fork, 0);
    cudaStreamWaitEvent(s2, e_fork, 0);
    cudaStreamWaitEvent(s3, e_fork, 0);

    eff_row<H_DIM><<<I_DIM, 256, 0, s1>>>(gate_w, gate_su, gate_sv, (__half*)pg);
    cudaEventRecord(e_j1, s1);
    eff_row<H_DIM><<<I_DIM, 256, 0, s2>>>(up_w, up_su, up_sv, (__half*)pu);
    cudaEventRecord(e_j2, s2);
    eff_row<I_DIM><<<H_DIM, 256, 0, s3>>>(down_w, down_su, down_sv, (__half*)pd);
    cudaEventRecord(e_j3, s3);

    x_to_half<<<592, 256>>>(x, (__half*)pxr, (size_t)M_DIM * H_DIM / 4);

    // gateup needs gate_eff + up_eff (+ xr via stream order)
    cudaStreamWaitEvent(0, e_j1, 0);
    cudaStreamWaitEvent(0, e_j2, 0);
    gemm_gateup<<<dim3(M_DIM / 128, I_DIM / 64), 256, GEMM_SMEM>>>();

    // down needs down_eff (eff_down overlapped with gateup)
    cudaStreamWaitEvent(0, e_j3, 0);
    gemm_down<<<dim3(M_DIM / 128, H_DIM / 128), 256, GEMM_SMEM>>>(out);
}